// round 17
// baseline (speedup 1.0000x reference)
#include <cuda_runtime.h>
#include <cuda_bf16.h>
#include <cuda_fp16.h>
#include <cstddef>
#include <cstdint>

// Problem dims
constexpr int BB = 4096;   // batch
constexpr int TT = 128;    // time
constexpr int HH = 156;    // hidden/nodes
constexpr int LL = 2;      // layers
constexpr int OO = 12;     // output len
constexpr int G4 = 4 * HH; // 624  (gate cols, ordered n' = 4*o + g; g: 0=i,1=f,2=c,3=o)
constexpr int NP = 640;    // padded gate width

// Scratch (device globals)
__device__ float g_ys[(size_t)BB * TT * HH];  // ~312 MiB

// Preprocessed data
__device__ float g_bsum[LL * NP];             // bx+bh in n' order
// fragment packs (single fp16): {b0, b1} per (n-tile, k-step, lane)
__device__ uint2 g_adjf2[20 * 10 * 32];       // adj^T fragments
__device__ uint2 g_wf2[LL * 80 * 10 * 32];    // h-weight fragments
__device__ uint2 g_wxf2[LL * 80 * 10 * 32];   // x-weight fragments

// ---------------- generic helpers ----------------
__device__ __forceinline__ float2 fma2(float2 d, float2 a, float2 b) {
    unsigned long long dd = *reinterpret_cast<unsigned long long*>(&d);
    unsigned long long aa = *reinterpret_cast<unsigned long long*>(&a);
    unsigned long long bb = *reinterpret_cast<unsigned long long*>(&b);
    asm("fma.rn.f32x2 %0, %1, %2, %0;" : "+l"(dd) : "l"(aa), "l"(bb));
    return *reinterpret_cast<float2*>(&dd);
}
// MUFU.TANH-based activations (sm_75+): one SFU op each
__device__ __forceinline__ float tanh_ap(float x) {
    float y;
    asm("tanh.approx.f32 %0, %1;" : "=f"(y) : "f"(x));
    return y;
}
__device__ __forceinline__ float sigmoid_ap(float x) {
    return fmaf(0.5f, tanh_ap(0.5f * x), 0.5f);
}
__device__ __forceinline__ uint32_t smem_u32(const void* p) {
    uint32_t a;
    asm("{ .reg .u64 t; cvta.to.shared.u64 t, %1; cvt.u32.u64 %0, t; }" : "=r"(a) : "l"(p));
    return a;
}
__device__ __forceinline__ uint32_t packh(float a, float b) {
    __half ha = __float2half_rn(a), hb = __float2half_rn(b);
    return (uint32_t)__half_as_ushort(ha) | ((uint32_t)__half_as_ushort(hb) << 16);
}
__device__ __forceinline__ void ldm_x4(uint32_t* r, uint32_t addr) {
    asm volatile("ldmatrix.sync.aligned.m8n8.x4.shared.b16 {%0,%1,%2,%3}, [%4];"
                 : "=r"(r[0]), "=r"(r[1]), "=r"(r[2]), "=r"(r[3]) : "r"(addr));
}
__device__ __forceinline__ void mma_f16(float* c, const uint32_t* a, uint32_t b0, uint32_t b1) {
    asm volatile(
        "mma.sync.aligned.m16n8k16.row.col.f32.f16.f16.f32 "
        "{%0,%1,%2,%3}, {%4,%5,%6,%7}, {%8,%9}, {%0,%1,%2,%3};"
        : "+f"(c[0]), "+f"(c[1]), "+f"(c[2]), "+f"(c[3])
        : "r"(a[0]), "r"(a[1]), "r"(a[2]), "r"(a[3]), "r"(b0), "r"(b1));
}

struct XArgs {
    const float* W[4];   // Wix, Wfx, Wcx, Wox   each [L,H,H]
    const float* bx[4];
    const float* bh[4];
};
struct HArgs {
    const float* W[4];   // Wih, Wfh, Wch, Woh  each [L,H,H]
};

// ---------------- setup kernels ----------------
__global__ __launch_bounds__(256) void setup_bsum(XArgs A) {
    int idx = blockIdx.x * 256 + threadIdx.x;
    if (idx >= LL * NP) return;
    int n = idx % NP, l = idx / NP;
    int o = n >> 2, g = n & 3;
    g_bsum[idx] = (o < HH) ? (A.bx[g][l * HH + o] + A.bh[g][l * HH + o]) : 0.f;
}
__global__ __launch_bounds__(256) void setup_adjf2(const float* __restrict__ adj) {
    int idx = blockIdx.x * 256 + threadIdx.x;
    if (idx >= 20 * 10 * 32) return;
    int lane = idx & 31, r = idx >> 5;
    int ks = r % 10, nt = r / 10;
    int gid = lane >> 2, tg = lane & 3;
    int n = nt * 8 + gid;           // output node
    int k0 = ks * 16 + 2 * tg;
    auto val = [&](int k) -> float { return (n < HH && k < HH) ? adj[n * HH + k] : 0.f; };
    g_adjf2[idx] = make_uint2(packh(val(k0), val(k0 + 1)), packh(val(k0 + 8), val(k0 + 9)));
}
__global__ __launch_bounds__(256) void setup_wf2(HArgs A) {
    int idx = blockIdx.x * 256 + threadIdx.x;
    if (idx >= LL * 80 * 10 * 32) return;
    int lane = idx & 31, r = idx >> 5;
    int ks = r % 10; r /= 10;
    int nt = r % 80;
    int l  = r / 80;
    int gid = lane >> 2, tg = lane & 3;
    int np = nt * 8 + gid;          // n' = 4*o + g
    int o = np >> 2, g = np & 3;
    int k0 = ks * 16 + 2 * tg;
    auto val = [&](int k) -> float {
        return (o < HH && k < HH) ? A.W[g][((size_t)l * HH + o) * HH + k] : 0.f;
    };
    g_wf2[idx] = make_uint2(packh(val(k0), val(k0 + 1)), packh(val(k0 + 8), val(k0 + 9)));
}
__global__ __launch_bounds__(256) void setup_wxf2(XArgs A) {
    int idx = blockIdx.x * 256 + threadIdx.x;
    if (idx >= LL * 80 * 10 * 32) return;
    int lane = idx & 31, r = idx >> 5;
    int ks = r % 10; r /= 10;
    int nt = r % 80;
    int l  = r / 80;
    int gid = lane >> 2, tg = lane & 3;
    int np = nt * 8 + gid;          // n' = 4*o + g
    int o = np >> 2, g = np & 3;
    int k0 = ks * 16 + 2 * tg;
    auto val = [&](int k) -> float {
        return (o < HH && k < HH) ? A.W[g][((size_t)l * HH + o) * HH + k] : 0.f;
    };
    g_wxf2[idx] = make_uint2(packh(val(k0), val(k0 + 1)), packh(val(k0 + 8), val(k0 + 9)));
}

// ---------------- shared layout constants ----------------
constexpr int SROWB = 336;                 // image row stride in bytes (168 fp16)
constexpr int IMGR = 16 * SROWB;           // 16-row image = 5376 B
constexpr int SM_BIAS = 5 * IMGR;          // bias floats after 5 images (h,c,t,u,x)
constexpr int RSMEM2 = SM_BIAS + NP * 4;   // 29440 B

// ---------------- the one big kernel: recurrence with fused x@Wx ----------------
__global__ __launch_bounds__(320, 4) void recur_mma(
        const float* __restrict__ x,
        const float* __restrict__ gw1, const float* __restrict__ gw2,
        float* __restrict__ out) {
    extern __shared__ char smem[];
    const uint32_t smb = smem_u32(smem);
    float* sbias = (float*)(smem + SM_BIAS);
    const int l = blockIdx.y;
    const int r0 = blockIdx.x * 16;
    const int tid = threadIdx.x, lane = tid & 31, wid = tid >> 5;  // 10 warps
    const int gid = lane >> 2, tg = lane & 3;
    const bool evenl = ((lane & 1) == 0);
    const uint32_t loff = (uint32_t)(((lane & 7) + 8 * ((lane >> 3) & 1)) * SROWB + (lane >> 4) * 16);

    for (int i = tid; i < (5 * IMGR) / 4; i += 320) ((uint32_t*)smem)[i] = 0u;
    for (int i = tid; i < NP; i += 320) sbias[i] = g_bsum[l * NP + i];
    __syncthreads();

    uint32_t hI = 0, cI = IMGR, tI = 2 * IMGR, uI = 3 * IMGR;
    const uint32_t xI = 4 * IMGR;

    const float c1 = gw1[l], c2 = gw2[l];
    const uint2* __restrict__ wf  = g_wf2  + (size_t)l * 80 * 10 * 32;
    const uint2* __restrict__ wxf = g_wxf2 + (size_t)l * 80 * 10 * 32;

    // ---- x staging: prefetch 16x156 fp32 into regs (2 x float4/thread) ----
    float4 xv4[2];
    int xr_[2], xc_[2];
    auto xfetch = [&](int t) {
#pragma unroll
        for (int i = 0; i < 2; ++i) {
            int idx = tid + 320 * i;            // need 16*39 = 624
            if (idx < 16 * 39) {
                int r = idx / 39, c4 = idx % 39;
                xr_[i] = r; xc_[i] = c4;
                xv4[i] = *(const float4*)(x + ((size_t)(r0 + r) * TT + t) * HH + 4 * c4);
            } else { xr_[i] = -1; xc_[i] = 0; xv4[i] = make_float4(0.f, 0.f, 0.f, 0.f); }
        }
    };
    auto xstore = [&]() {
#pragma unroll
        for (int i = 0; i < 2; ++i) {
            if (xr_[i] >= 0) {
                uint2 p = make_uint2(packh(xv4[i].x, xv4[i].y), packh(xv4[i].z, xv4[i].w));
                *(uint2*)(smem + xI + xr_[i] * SROWB + 8 * xc_[i]) = p;
            }
        }
    };

    // fused GCN half-step on TWO states (single fp16 images, 16 rows)
    auto gcn2 = [&](uint32_t aI, uint32_t bI, uint32_t oaI, uint32_t obI,
                    float w, bool rl) {
        float accA[2][4], accB[2][4];
#pragma unroll
        for (int j = 0; j < 2; j++)
#pragma unroll
            for (int q = 0; q < 4; q++) { accA[j][q] = 0.f; accB[j][q] = 0.f; }
#pragma unroll 1
        for (int ks = 0; ks < 10; ++ks) {
            uint2 B0 = g_adjf2[((size_t)wid * 10 + ks) * 32 + lane];
            uint2 B1 = g_adjf2[((size_t)(wid + 10) * 10 + ks) * 32 + lane];
            uint32_t Fa[4], Fb[4];
            ldm_x4(Fa, smb + aI + (uint32_t)(ks * 32) + loff);
            ldm_x4(Fb, smb + bI + (uint32_t)(ks * 32) + loff);
            mma_f16(accA[0], Fa, B0.x, B0.y);
            mma_f16(accA[1], Fa, B1.x, B1.y);
            mma_f16(accB[0], Fb, B0.x, B0.y);
            mma_f16(accB[1], Fb, B1.x, B1.y);
        }
#pragma unroll
        for (int j = 0; j < 2; j++) {
            int colByte = ((wid + 10 * j) * 8 + 2 * tg) * 2;
            int rb0 = gid * SROWB + colByte;
            int rb1 = rb0 + 8 * SROWB;
            {
                float v0 = w * accA[j][0], v1 = w * accA[j][1];
                float v2 = w * accA[j][2], v3 = w * accA[j][3];
                if (rl) { v0 = fmaxf(v0, 0.f); v1 = fmaxf(v1, 0.f); v2 = fmaxf(v2, 0.f); v3 = fmaxf(v3, 0.f); }
                else    { v0 = sigmoid_ap(v0);  v1 = sigmoid_ap(v1);  v2 = sigmoid_ap(v2);  v3 = sigmoid_ap(v3); }
                *(uint32_t*)(smem + oaI + rb0) = packh(v0, v1);
                *(uint32_t*)(smem + oaI + rb1) = packh(v2, v3);
            }
            {
                float v0 = w * accB[j][0], v1 = w * accB[j][1];
                float v2 = w * accB[j][2], v3 = w * accB[j][3];
                if (rl) { v0 = fmaxf(v0, 0.f); v1 = fmaxf(v1, 0.f); v2 = fmaxf(v2, 0.f); v3 = fmaxf(v3, 0.f); }
                else    { v0 = sigmoid_ap(v0);  v1 = sigmoid_ap(v1);  v2 = sigmoid_ap(v2);  v3 = sigmoid_ap(v3); }
                *(uint32_t*)(smem + obI + rb0) = packh(v0, v1);
                *(uint32_t*)(smem + obI + rb1) = packh(v2, v3);
            }
        }
    };

    // gates: preacts = h @ Wh^T + x_t @ Wx^T + bias (n' = 4o+g); cell update in-register
    auto gates = [&](int t) {
#pragma unroll 1
        for (int hf = 0; hf < 2; ++hf) {
            float acc[4][4];
#pragma unroll
            for (int u = 0; u < 4; u++)
#pragma unroll
                for (int q = 0; q < 4; q++) acc[u][q] = 0.f;
            // merged K-loop: h-side + x-side (both single fp16)
#pragma unroll 1
            for (int ks = 0; ks < 10; ++ks) {
                uint32_t Ah[4], Ax[4];
                ldm_x4(Ah, smb + hI + (uint32_t)(ks * 32) + loff);
                ldm_x4(Ax, smb + xI + (uint32_t)(ks * 32) + loff);
#pragma unroll
                for (int u = 0; u < 4; ++u) {
                    int nt = wid + 10 * (4 * hf + u);
                    uint2 Bh = wf[((size_t)nt * 10 + ks) * 32 + lane];
                    uint2 Bx = wxf[((size_t)nt * 10 + ks) * 32 + lane];
                    mma_f16(acc[u], Ah, Bh.x, Bh.y);
                    mma_f16(acc[u], Ax, Bx.x, Bx.y);
                }
            }
#pragma unroll
            for (int u = 0; u < 4; ++u) {
                int nt = wid + 10 * (4 * hf + u);
                int o = 2 * nt + (tg >> 1);
                float a0 = acc[u][0], a1 = acc[u][1];
                float a2 = acc[u][2], a3 = acc[u][3];
                float e0 = __shfl_xor_sync(0xffffffffu, a0, 1);
                float e1 = __shfl_xor_sync(0xffffffffu, a1, 1);
                float e2 = __shfl_xor_sync(0xffffffffu, a2, 1);
                float e3 = __shfl_xor_sync(0xffffffffu, a3, 1);
                if (o < HH) {
                    int row = gid + (evenl ? 0 : 8);
                    float pi = evenl ? a0 : e2;
                    float pf = evenl ? a1 : e3;
                    float pc = evenl ? e0 : a2;
                    float po = evenl ? e1 : a3;
                    const float4 bv = *(const float4*)(sbias + 4 * o);
                    float it = sigmoid_ap(pi + bv.x);
                    float ft = sigmoid_ap(pf + bv.y);
                    float cb = tanh_ap(pc + bv.z);
                    float ot = sigmoid_ap(po + bv.w);
                    int sb = row * SROWB + 2 * o;
                    float cold = __half2float(*(__half*)(smem + cI + sb));
                    float ct = ft * cold + it * cb;
                    float hn = ot * tanh_ap(ct);
                    *(__half*)(smem + cI + sb) = __float2half_rn(ct);
                    *(__half*)(smem + tI + sb) = __float2half_rn(hn);
                    if (l == 1) g_ys[((size_t)(r0 + row) * TT + t) * HH + o] = hn;
                }
            }
        }
    };

    // stage x_0
    xfetch(0); xstore();
    __syncthreads();

    for (int t = 0; t < TT; ++t) {
        if (t > 0) {
            xfetch(t);                                 // LDGs issue, drain behind gcn mma
            gcn2(hI, cI, tI, uI, c1, true);
            xstore();                                  // x_t image ready before barrier
            __syncthreads();
            gcn2(tI, uI, hI, cI, c2, false); __syncthreads();
        }
        gates(t);                      // reads h,x (mma) + c (cold); writes c (ct), T (new h)
        __syncthreads();
        uint32_t s = hI; hI = tI; tI = s;
    }

    // final states -> h_n, c_n
    constexpr size_t OUT0 = (size_t)BB * OO * HH;
    constexpr size_t HN   = (size_t)LL * BB * HH;
    for (int i = tid; i < 16 * HH; i += 320) {
        int m = i / HH, o = i - m * HH;
        int sb = m * SROWB + 2 * o;
        float hv = __half2float(*(__half*)(smem + hI + sb));
        float cv = __half2float(*(__half*)(smem + cI + sb));
        size_t off = ((size_t)l * BB + (r0 + m)) * HH + o;
        out[OUT0 + off]      = hv;
        out[OUT0 + HN + off] = cv;
    }
}

// ---------------- kernel 3: output projection ----------------
constexpr int YROW = TT * HH;  // 19968
constexpr int OSMEM = (YROW + OO * TT + OO) * 4;

__global__ __launch_bounds__(256) void out_kernel(const float* __restrict__ Wout,
                                                  const float* __restrict__ bout,
                                                  float* __restrict__ out) {
    extern __shared__ float sm[];
    float* sy = sm;
    float* sw = sm + YROW;
    float* sb = sw + OO * TT;
    const int b = blockIdx.x;
    const int tid = threadIdx.x;
    const float* yb = g_ys + (size_t)b * YROW;
    for (int i = tid; i < YROW / 4; i += 256) ((float4*)sy)[i] = ((const float4*)yb)[i];
    for (int i = tid; i < OO * TT; i += 256) sw[i] = Wout[i];
    if (tid < OO) sb[tid] = bout[tid];
    __syncthreads();
    for (int idx = tid; idx < HH * OO; idx += 256) {
        int f = idx / OO, jj = idx - f * OO;
        const float* yr = sy + f * TT;
        const float* wr = sw + jj * TT;
        float2 a = make_float2(0.f, 0.f);
#pragma unroll 4
        for (int p = 0; p < TT / 2; ++p)
            a = fma2(a, *(const float2*)(yr + 2 * p), *(const float2*)(wr + 2 * p));
        out[(size_t)b * (HH * OO) + idx] = a.x + a.y + sb[jj];
    }
}

// ---------------- launcher ----------------
extern "C" void kernel_launch(void* const* d_in, const int* in_sizes, int n_in,
                              void* d_out, int out_size) {
    const float* x   = (const float*)d_in[0];
    const float* adj = (const float*)d_in[1];

    XArgs xa;
    xa.W[0] = (const float*)d_in[2];  xa.bx[0] = (const float*)d_in[3];
    xa.W[1] = (const float*)d_in[6];  xa.bx[1] = (const float*)d_in[7];
    xa.W[2] = (const float*)d_in[10]; xa.bx[2] = (const float*)d_in[11];
    xa.W[3] = (const float*)d_in[14]; xa.bx[3] = (const float*)d_in[15];
    xa.bh[0] = (const float*)d_in[5];
    xa.bh[1] = (const float*)d_in[9];
    xa.bh[2] = (const float*)d_in[13];
    xa.bh[3] = (const float*)d_in[17];

    HArgs ha;
    ha.W[0] = (const float*)d_in[4];
    ha.W[1] = (const float*)d_in[8];
    ha.W[2] = (const float*)d_in[12];
    ha.W[3] = (const float*)d_in[16];

    const float* gw1  = (const float*)d_in[18];
    const float* gw2  = (const float*)d_in[19];
    const float* Wout = (const float*)d_in[20];
    const float* bout = (const float*)d_in[21];
    float* out = (float*)d_out;

    cudaFuncSetAttribute(recur_mma,  cudaFuncAttributeMaxDynamicSharedMemorySize, RSMEM2);
    cudaFuncSetAttribute(out_kernel, cudaFuncAttributeMaxDynamicSharedMemorySize, OSMEM);

    setup_bsum <<<(LL * NP + 255) / 256, 256>>>(xa);
    setup_adjf2<<<(20 * 10 * 32 + 255) / 256, 256>>>(adj);
    setup_wf2  <<<(LL * 80 * 10 * 32 + 255) / 256, 256>>>(ha);
    setup_wxf2 <<<(LL * 80 * 10 * 32 + 255) / 256, 256>>>(xa);

    dim3 rg(BB / 16, LL);                    // 256 x 2 = 512 blocks, up to 4/SM resident
    recur_mma<<<rg, 320, RSMEM2>>>(x, gw1, gw2, out);

    out_kernel<<<BB, 256, OSMEM>>>(Wout, bout, out);
}